// round 12
// baseline (speedup 1.0000x reference)
#include <cuda_runtime.h>
#include <math.h>

#define B    16384
#define D    1024
#define KC   15
#define C    1000
#define NMOD 3

#define SEG_ROWS 112   // grid (4,148): 148*112 = 16576 >= B

// ---------------- scratch (device globals; no allocation) ----------------
__device__ float g_avg[NMOD][B];
__device__ int   g_assign[NMOD][B];
__device__ float g_rmax[B];
__device__ float g_rinv[B];
__device__ float g_segsum[NMOD * KC][C];   // 180 KB, L2-resident
__device__ float g_entpart[NMOD * KC];
__device__ float g_attrpart[NMOD];
__device__ int   g_ticket;

__device__ __forceinline__ unsigned f2tf32(float x) {
    unsigned r; asm("cvt.rna.tf32.f32 %0, %1;" : "=r"(r) : "f"(x)); return r;
}
__device__ __forceinline__ void mma_tf32(float c[4], unsigned a0, unsigned a1,
                                         unsigned a2, unsigned a3,
                                         unsigned b0, unsigned b1) {
    asm volatile(
        "mma.sync.aligned.m16n8k8.row.col.f32.tf32.tf32.f32 "
        "{%0,%1,%2,%3}, {%4,%5,%6,%7}, {%8,%9}, {%0,%1,%2,%3};\n"
        : "+f"(c[0]), "+f"(c[1]), "+f"(c[2]), "+f"(c[3])
        : "r"(a0), "r"(a1), "r"(a2), "r"(a3), "r"(b0), "r"(b1));
}

// ---------------- #1 (s1): zero segsum + ticket ----------------
__global__ void init_kernel() {
    int i = blockIdx.x * blockDim.x + threadIdx.x;
    if (i < NMOD * KC * C) ((float*)g_segsum)[i] = 0.f;
    if (i == 0) g_ticket = 0;
}

// ---------------- #2 (s1): softmax stats only ----------------
__global__ __launch_bounds__(256) void stats_kernel(const float* __restrict__ outp) {
    int warp = threadIdx.x >> 5, lane = threadIdx.x & 31;
    int row = blockIdx.x * 8 + warp;
    const float4* r4 = (const float4*)(outp + (size_t)row * C);
    float4 a[8];
    float m = -INFINITY;
#pragma unroll
    for (int i = 0; i < 8; i++) {
        int j = lane + i * 32;
        if (j < C / 4) {
            float4 x = r4[j]; a[i] = x;
            m = fmaxf(m, fmaxf(fmaxf(x.x, x.y), fmaxf(x.z, x.w)));
        }
    }
#pragma unroll
    for (int o = 16; o > 0; o >>= 1) m = fmaxf(m, __shfl_xor_sync(0xffffffffu, m, o));
    float s = 0.f;
#pragma unroll
    for (int i = 0; i < 8; i++) {
        int j = lane + i * 32;
        if (j < C / 4)
            s += __expf(a[i].x - m) + __expf(a[i].y - m) + __expf(a[i].z - m) + __expf(a[i].w - m);
    }
#pragma unroll
    for (int o = 16; o > 0; o >>= 1) s += __shfl_xor_sync(0xffffffffu, s, o);
    if (lane == 0) { g_rmax[row] = m; g_rinv[row] = 1.f / s; }
}

// ---------------- #3 (s1): pure copy out -> d_out ----------------
__global__ __launch_bounds__(256) void copy_kernel(const float* __restrict__ src,
                                                   float* __restrict__ dst) {
    size_t i = (size_t)blockIdx.x * 256 + threadIdx.x;
    size_t n4 = (size_t)B * C / 4;
    const float4* s4 = (const float4*)src;
    float4* d4 = (float4*)dst;
    for (; i < n4; i += (size_t)gridDim.x * 256) d4[i] = s4[i];
}

// ---------------- #4 (main, PROFILED): similarities via tf32 MMA ----------
// 64 rows/block, grid (256, 3) = 5.2 blocks/SM target; 4 resident (regs<=64).
// Warp w owns m-tile (w&3), n-tile (w>>2): one m16n8k8 per k-step.
#define SROWS   64
#define KCHUNK  64
#define ASTR    68   // 68 mod 32 == 4: conflict-free frag LDS (banks 4g+tig)
#define BSTR    24
__global__ __launch_bounds__(256, 4) void sim_kernel(
    const float* __restrict__ f0, const float* __restrict__ f1, const float* __restrict__ f2,
    const float* __restrict__ c0, const float* __restrict__ c1, const float* __restrict__ c2) {
    int mod = blockIdx.y;
    const float* fea = mod == 0 ? f0 : (mod == 1 ? f1 : f2);
    const float* cen = mod == 0 ? c0 : (mod == 1 ? c1 : c2);
    int tid = threadIdx.x;
    int lane = tid & 31, w = tid >> 5;
    int g = lane >> 2, tig = lane & 3;
    int mt = w & 3, nt = w >> 2;

    __shared__ unsigned As[SROWS * ASTR];    // 17408 B
    __shared__ unsigned Bs[KCHUNK * BSTR];   // 6144 B
    __shared__ float nrm_s[SROWS];
    __shared__ float cns[16];
    __shared__ float cninv[16];
    __shared__ float sims[SROWS][17];        // raw dots, padded

    int row0 = blockIdx.x * SROWS;

    // A loader: thread -> row tid>>2, float4 cols (tid&3) + 4p (p=0..3)
    int lr = tid >> 2;
    int lq = tid & 3;
    // B loader: warp w loads n=w (and n=w+8), kk = lane and lane+32
    int bkk = lane;

    float nacc = 0.f;
    float cnacc0 = 0.f, cnacc1 = 0.f;
    float cfr[4] = {0.f, 0.f, 0.f, 0.f};

    // prefetch chunk 0
    float4 ar[4];
    float br0a, br0b, br1a, br1b;
#pragma unroll
    for (int p = 0; p < 4; p++)
        ar[p] = *(const float4*)(fea + (size_t)(row0 + lr) * D + (lq + p * 4) * 4);
    br0a = cen[(size_t)w * D + bkk];
    br0b = cen[(size_t)w * D + bkk + 32];
    br1a = (w + 8 < KC) ? cen[(size_t)(w + 8) * D + bkk] : 0.f;
    br1b = (w + 8 < KC) ? cen[(size_t)(w + 8) * D + bkk + 32] : 0.f;

    for (int kb = 0; kb < D; kb += KCHUNK) {
        // norms (fp32, exact) + cvt + stage
#pragma unroll
        for (int p = 0; p < 4; p++) {
            float4 v = ar[p];
            nacc += v.x * v.x + v.y * v.y + v.z * v.z + v.w * v.w;
            unsigned* dst = &As[lr * ASTR + (lq + p * 4) * 4];
            uint4 u;
            u.x = f2tf32(v.x); u.y = f2tf32(v.y); u.z = f2tf32(v.z); u.w = f2tf32(v.w);
            *(uint4*)dst = u;
        }
        cnacc0 += br0a * br0a + br0b * br0b;
        cnacc1 += br1a * br1a + br1b * br1b;
        Bs[bkk * BSTR + w]            = f2tf32(br0a);
        Bs[(bkk + 32) * BSTR + w]     = f2tf32(br0b);
        Bs[bkk * BSTR + w + 8]        = f2tf32(br1a);
        Bs[(bkk + 32) * BSTR + w + 8] = f2tf32(br1b);
        __syncthreads();

        // prefetch next chunk (4 LDG.128 in flight through the mma section)
        if (kb + KCHUNK < D) {
            int nb = kb + KCHUNK;
#pragma unroll
            for (int p = 0; p < 4; p++)
                ar[p] = *(const float4*)(fea + (size_t)(row0 + lr) * D + nb + (lq + p * 4) * 4);
            br0a = cen[(size_t)w * D + nb + bkk];
            br0b = cen[(size_t)w * D + nb + bkk + 32];
            br1a = (w + 8 < KC) ? cen[(size_t)(w + 8) * D + nb + bkk] : 0.f;
            br1b = (w + 8 < KC) ? cen[(size_t)(w + 8) * D + nb + bkk + 32] : 0.f;
        }

        // 8 k-steps, one m16n8k8 per step
#pragma unroll
        for (int ks = 0; ks < KCHUNK; ks += 8) {
            unsigned a0 = As[(mt * 16 + g) * ASTR + ks + tig];
            unsigned a1 = As[(mt * 16 + g + 8) * ASTR + ks + tig];
            unsigned a2 = As[(mt * 16 + g) * ASTR + ks + tig + 4];
            unsigned a3 = As[(mt * 16 + g + 8) * ASTR + ks + tig + 4];
            unsigned b0 = Bs[(ks + tig) * BSTR + nt * 8 + g];
            unsigned b1 = Bs[(ks + tig + 4) * BSTR + nt * 8 + g];
            mma_tf32(cfr, a0, a1, a2, a3, b0, b1);
        }
        __syncthreads();
    }

    // row norms: 4 consecutive lanes share a row
    {
        float v = nacc;
        v += __shfl_xor_sync(0xffffffffu, v, 1);
        v += __shfl_xor_sync(0xffffffffu, v, 2);
        if ((tid & 3) == 0) nrm_s[lr] = v;
    }
    // centroid norms
    {
        float v0 = cnacc0, v1 = cnacc1;
#pragma unroll
        for (int o = 16; o > 0; o >>= 1) {
            v0 += __shfl_xor_sync(0xffffffffu, v0, o);
            v1 += __shfl_xor_sync(0xffffffffu, v1, o);
        }
        if (lane == 0) { cns[w] = v0; cns[w + 8] = v1; }
    }
    // stage raw dots to smem
    {
        int r_lo = mt * 16 + g, r_hi = r_lo + 8;
        int ca = nt * 8 + 2 * tig, cb = ca + 1;
        sims[r_lo][ca] = cfr[0];
        sims[r_lo][cb] = cfr[1];
        sims[r_hi][ca] = cfr[2];
        sims[r_hi][cb] = cfr[3];
    }
    __syncthreads();
    if (tid < 16) cninv[tid] = 1.f / fmaxf(sqrtf(cns[tid]), 1e-12f);
    __syncthreads();

    // finalize: one thread per row, exact first-max argmax
    if (tid < SROWS) {
        int r = tid;
        float fin = 1.f / fmaxf(sqrtf(nrm_s[r]), 1e-12f);
        float best = -1e30f; int bi = 0; float sum = 0.f;
#pragma unroll
        for (int k = 0; k < KC; k++) {
            float sim = sims[r][k] * fin * cninv[k];
            sum += sim;
            if (sim > best) { best = sim; bi = k; }
        }
        g_avg[mod][row0 + r] = sum * (1.0f / KC);
        g_assign[mod][row0 + r] = bi;
    }
}

// ---------------- #5 (s2): radix select + attractive (smem-resident) ------
__global__ __launch_bounds__(1024) void select_attr_kernel(int rank0) {
    extern __shared__ unsigned int skeys[];       // 16384 u32 = 64 KB
    __shared__ unsigned int hist[256];
    __shared__ unsigned int sc[256];
    __shared__ unsigned int s_prefix;
    __shared__ int s_rank;
    __shared__ float s_thr;
    __shared__ float sred[32];

    int mod = blockIdx.x;
    const float* avg = g_avg[mod];
    int tid = threadIdx.x;
    int lane = tid & 31, warp = tid >> 5;

#pragma unroll
    for (int i = tid; i < B; i += 1024) {
        unsigned int u = __float_as_uint(avg[i]);
        skeys[i] = (u & 0x80000000u) ? ~u : (u | 0x80000000u);
    }
    if (tid == 0) { s_prefix = 0u; s_rank = rank0; }
    __syncthreads();

    for (int p = 3; p >= 0; p--) {
        if (tid < 256) hist[tid] = 0u;
        __syncthreads();
        unsigned int mask = (p == 3) ? 0u : (0xFFFFFFFFu << ((p + 1) * 8));
        unsigned int pref = s_prefix;
        int r = s_rank;
#pragma unroll
        for (int i = tid; i < B; i += 1024) {
            unsigned int u = skeys[i];
            if ((u & mask) == (pref & mask))
                atomicAdd(&hist[(u >> (p * 8)) & 255u], 1u);
        }
        __syncthreads();
        if (tid < 256) sc[tid] = hist[tid];
        __syncthreads();
#pragma unroll
        for (int off = 1; off < 256; off <<= 1) {
            unsigned int add = 0u;
            if (tid < 256 && tid >= off) add = sc[tid - off];
            __syncthreads();
            if (tid < 256) sc[tid] += add;
            __syncthreads();
        }
        if (tid < 256) {
            unsigned int inc = sc[tid], exc = inc - hist[tid];
            if ((unsigned int)r >= exc && (unsigned int)r < inc) {
                s_prefix = pref | ((unsigned int)tid << (p * 8));
                s_rank = r - (int)exc;
            }
        }
        __syncthreads();
    }
    if (tid == 0) {
        unsigned int u = s_prefix;
        unsigned int bits = (u & 0x80000000u) ? (u ^ 0x80000000u) : ~u;
        s_thr = __uint_as_float(bits);
    }
    __syncthreads();

    float thr = s_thr;
    float s = 0.f;
#pragma unroll
    for (int i = tid; i < B; i += 1024) {
        unsigned int u = skeys[i];
        unsigned int bits = (u & 0x80000000u) ? (u ^ 0x80000000u) : ~u;
        float a = __uint_as_float(bits);
        float w = 1.f / (1.f + expf(-5.0f * (a - thr)));   // ALPHA = 5
        s += w * (1.f - a);
    }
#pragma unroll
    for (int o = 16; o > 0; o >>= 1) s += __shfl_xor_sync(0xffffffffu, s, o);
    if (lane == 0) sred[warp] = s;
    __syncthreads();
    if (tid < 32) {
        float t = sred[tid];
#pragma unroll
        for (int o = 16; o > 0; o >>= 1) t += __shfl_xor_sync(0xffffffffu, t, o);
        if (tid == 0) g_attrpart[mod] = t;
    }
}

// ---------------- #6 (main): segment sums, 16-row unroll, L2 atomics ------
#define SEG_CHUNK 64
__global__ __launch_bounds__(256, 4) void seg_kernel(const float* __restrict__ outp) {
    __shared__ float acc[NMOD * KC * 256];   // 46080 B
    __shared__ int   s_a0[SEG_CHUNK], s_a1[SEG_CHUNK], s_a2[SEG_CHUNK];
    __shared__ float s_rm[SEG_CHUNK], s_ri[SEG_CHUNK];
    int tid = threadIdx.x;
    int c = blockIdx.x * 256 + tid;
    bool valid = c < C;
    for (int j = tid; j < NMOD * KC * 256; j += 256) acc[j] = 0.f;

    int r0 = blockIdx.y * SEG_ROWS;
    int rend = r0 + SEG_ROWS; if (rend > B) rend = B;

    for (int cb = r0; cb < rend; cb += SEG_CHUNK) {
        int clen = rend - cb; if (clen > SEG_CHUNK) clen = SEG_CHUNK;  // mult of 16
        __syncthreads();
        if (tid < clen) {
            s_a0[tid] = g_assign[0][cb + tid] * 256;
            s_a1[tid] = (KC + g_assign[1][cb + tid]) * 256;
            s_a2[tid] = (2 * KC + g_assign[2][cb + tid]) * 256;
            s_rm[tid] = g_rmax[cb + tid];
            s_ri[tid] = g_rinv[cb + tid];
        }
        __syncthreads();
        if (valid) {
            const float* op = outp + (size_t)cb * C + c;
            for (int rr = 0; rr < clen; rr += 16) {
                float p[16];
#pragma unroll
                for (int j = 0; j < 16; j++)
                    p[j] = op[(size_t)(rr + j) * C];           // 16 loads in flight
#pragma unroll
                for (int j = 0; j < 16; j++)
                    p[j] = __expf(p[j] - s_rm[rr + j]) * s_ri[rr + j];
#pragma unroll
                for (int j = 0; j < 16; j++) {
                    acc[s_a0[rr + j] + tid] += p[j];
                    acc[s_a1[rr + j] + tid] += p[j];
                    acc[s_a2[rr + j] + tid] += p[j];
                }
            }
        }
    }
    __syncthreads();
    if (valid) {
#pragma unroll
        for (int j = 0; j < NMOD * KC; j++)
            atomicAdd(&g_segsum[j][c], acc[j * 256 + tid]);
    }
}

// ---------------- #7 (main): entropy + counts + finalize (ticket) ---------
__global__ void entropy_final_kernel(float* dout_last) {
    int bk = blockIdx.x;  // 0..44
    int mod = bk / KC, k = bk % KC;
    int tid = threadIdx.x;

    int cnt = 0;
    const int* as = g_assign[mod];
    for (int i = tid; i < B; i += 256) cnt += (as[i] == k);
    __shared__ int ci[256];
    ci[tid] = cnt; __syncthreads();
    for (int o = 128; o > 0; o >>= 1) {
        if (tid < o) ci[tid] += ci[tid + o];
        __syncthreads();
    }
    float fcnt = (float)ci[0];
    float inv = 1.f / fmaxf(fcnt, 1.f);

    float s = 0.f;
    for (int i = tid; i < C; i += 256) {
        float mp = g_segsum[bk][i] * inv;
        s += mp * __logf(mp + 1e-8f);
    }
    __shared__ float sm[256];
    sm[tid] = s; __syncthreads();
    for (int o = 128; o > 0; o >>= 1) {
        if (tid < o) sm[tid] += sm[tid + o];
        __syncthreads();
    }
    if (tid == 0) {
        g_entpart[bk] = (fcnt >= 3.0f) ? sm[0] : 0.f;
        __threadfence();
        int t = atomicAdd(&g_ticket, 1);
        if (t == NMOD * KC - 1) {
            __threadfence();
            float div = 0.f;
#pragma unroll
            for (int j = 0; j < NMOD * KC; j++) div += g_entpart[j];
            float attr = g_attrpart[0] + g_attrpart[1] + g_attrpart[2];
            // LAM_CLUSTER = 6.0, LAM_DIV = 0.1
            *dout_last = 6.0f * (attr / (float)B) + 0.1f * div;
        }
    }
}

// ---------------- launch: fork-join multi-stream graph --------------------
extern "C" void kernel_launch(void* const* d_in, const int* in_sizes, int n_in,
                              void* d_out, int out_size) {
    const float* f0 = (const float*)d_in[0];
    const float* f1 = (const float*)d_in[1];
    const float* f2 = (const float*)d_in[2];
    const float* c0 = (const float*)d_in[3];
    const float* c1 = (const float*)d_in[4];
    const float* c2 = (const float*)d_in[5];
    const float* outp = (const float*)d_in[6];
    float* dout = (float*)d_out;
    (void)n_in; (void)in_sizes;

    static cudaStream_t s1 = 0, s2 = 0;
    static cudaEvent_t ev_root = 0, ev_stats = 0, ev_copy = 0, ev_sim = 0, ev_sel = 0;
    if (s1 == 0) {
        cudaStreamCreateWithFlags(&s1, cudaStreamNonBlocking);
        cudaStreamCreateWithFlags(&s2, cudaStreamNonBlocking);
        cudaEventCreateWithFlags(&ev_root, cudaEventDisableTiming);
        cudaEventCreateWithFlags(&ev_stats, cudaEventDisableTiming);
        cudaEventCreateWithFlags(&ev_copy, cudaEventDisableTiming);
        cudaEventCreateWithFlags(&ev_sim, cudaEventDisableTiming);
        cudaEventCreateWithFlags(&ev_sel, cudaEventDisableTiming);
        cudaFuncSetAttribute(select_attr_kernel,
                             cudaFuncAttributeMaxDynamicSharedMemorySize, B * 4);
    }

    // fork to s1: init + stats + copy (independent of sim)
    cudaEventRecord(ev_root, 0);
    cudaStreamWaitEvent(s1, ev_root, 0);
    init_kernel<<<(NMOD * KC * C + 255) / 256, 256, 0, s1>>>();             // #1
    stats_kernel<<<B / 8, 256, 0, s1>>>(outp);                              // #2
    cudaEventRecord(ev_stats, s1);
    copy_kernel<<<2048, 256, 0, s1>>>(outp, dout);                          // #3
    cudaEventRecord(ev_copy, s1);

    // main: sim via tf32 MMA (profiled slot #4)
    sim_kernel<<<dim3(B / SROWS, NMOD), 256>>>(f0, f1, f2, c0, c1, c2);     // #4

    // fork to s2: select (depends only on sim)
    cudaEventRecord(ev_sim, 0);
    cudaStreamWaitEvent(s2, ev_sim, 0);
    int rank0 = B - (int)((double)B * 0.6);   // = 6554
    select_attr_kernel<<<NMOD, 1024, B * 4, s2>>>(rank0);                   // #5
    cudaEventRecord(ev_sel, s2);

    // main: seg needs stats(+init) + assigns(sim, same stream)
    cudaStreamWaitEvent(0, ev_stats, 0);
    seg_kernel<<<dim3(4, 148), 256>>>(outp);                                // #6

    // join select + copy, then entropy+finalize
    cudaStreamWaitEvent(0, ev_sel, 0);
    cudaStreamWaitEvent(0, ev_copy, 0);
    entropy_final_kernel<<<NMOD * KC, 256>>>(dout + (size_t)out_size - 1);  // #7
}

// round 13
// speedup vs baseline: 1.0374x; 1.0374x over previous
#include <cuda_runtime.h>
#include <math.h>

#define B    16384
#define D    1024
#define KC   15
#define C    1000
#define NMOD 3

#define SEG_ROWS 112   // grid (4,148): 148*112 = 16576 >= B

// ---------------- scratch (device globals; no allocation) ----------------
__device__ float g_avg[NMOD][B];
__device__ int   g_assign[NMOD][B];
__device__ float g_rmax[B];
__device__ float g_rinv[B];
__device__ float g_segsum[NMOD * KC][C];   // 180 KB, L2-resident
__device__ float g_entpart[NMOD * KC];
__device__ float g_attrpart[NMOD];
__device__ int   g_ticket;
// K-split partials (L2-resident between sim and sim_fin)
__device__ float g_pdot[2][NMOD][B][16];   // 6.3 MB
__device__ float g_pnrm[2][NMOD][B];
__device__ float g_pcn[2][NMOD][16];

__device__ __forceinline__ unsigned f2tf32(float x) {
    unsigned r; asm("cvt.rna.tf32.f32 %0, %1;" : "=r"(r) : "f"(x)); return r;
}
__device__ __forceinline__ void mma_tf32(float c[4], unsigned a0, unsigned a1,
                                         unsigned a2, unsigned a3,
                                         unsigned b0, unsigned b1) {
    asm volatile(
        "mma.sync.aligned.m16n8k8.row.col.f32.tf32.tf32.f32 "
        "{%0,%1,%2,%3}, {%4,%5,%6,%7}, {%8,%9}, {%0,%1,%2,%3};\n"
        : "+f"(c[0]), "+f"(c[1]), "+f"(c[2]), "+f"(c[3])
        : "r"(a0), "r"(a1), "r"(a2), "r"(a3), "r"(b0), "r"(b1));
}

// ---------------- #1 (s1): zero segsum + ticket ----------------
__global__ void init_kernel() {
    int i = blockIdx.x * blockDim.x + threadIdx.x;
    if (i < NMOD * KC * C) ((float*)g_segsum)[i] = 0.f;
    if (i == 0) g_ticket = 0;
}

// ---------------- #2 (s1): softmax stats only ----------------
__global__ __launch_bounds__(256) void stats_kernel(const float* __restrict__ outp) {
    int warp = threadIdx.x >> 5, lane = threadIdx.x & 31;
    int row = blockIdx.x * 8 + warp;
    const float4* r4 = (const float4*)(outp + (size_t)row * C);
    float4 a[8];
    float m = -INFINITY;
#pragma unroll
    for (int i = 0; i < 8; i++) {
        int j = lane + i * 32;
        if (j < C / 4) {
            float4 x = r4[j]; a[i] = x;
            m = fmaxf(m, fmaxf(fmaxf(x.x, x.y), fmaxf(x.z, x.w)));
        }
    }
#pragma unroll
    for (int o = 16; o > 0; o >>= 1) m = fmaxf(m, __shfl_xor_sync(0xffffffffu, m, o));
    float s = 0.f;
#pragma unroll
    for (int i = 0; i < 8; i++) {
        int j = lane + i * 32;
        if (j < C / 4)
            s += __expf(a[i].x - m) + __expf(a[i].y - m) + __expf(a[i].z - m) + __expf(a[i].w - m);
    }
#pragma unroll
    for (int o = 16; o > 0; o >>= 1) s += __shfl_xor_sync(0xffffffffu, s, o);
    if (lane == 0) { g_rmax[row] = m; g_rinv[row] = 1.f / s; }
}

// ---------------- #3 (s1): pure copy out -> d_out ----------------
__global__ __launch_bounds__(256) void copy_kernel(const float* __restrict__ src,
                                                   float* __restrict__ dst) {
    size_t i = (size_t)blockIdx.x * 256 + threadIdx.x;
    size_t n4 = (size_t)B * C / 4;
    const float4* s4 = (const float4*)src;
    float4* d4 = (float4*)dst;
    for (; i < n4; i += (size_t)gridDim.x * 256) d4[i] = s4[i];
}

// ---------------- #4 (main, PROFILED): K-split tf32 MMA similarities ------
// grid (B/128, 3, 2): R10 tile geometry (validated coalescing), each block
// covers 512 of D; 4 blocks/SM resident. Writes partial dots/norms.
#define KCHUNK  32
#define DHALF   512
#define ASTR    36   // conflict-free frag LDS
#define BSTR    24
__global__ __launch_bounds__(256, 4) void sim_kernel(
    const float* __restrict__ f0, const float* __restrict__ f1, const float* __restrict__ f2,
    const float* __restrict__ c0, const float* __restrict__ c1, const float* __restrict__ c2) {
    int mod = blockIdx.y;
    int z = blockIdx.z;
    int kbase = z * DHALF;
    const float* fea = mod == 0 ? f0 : (mod == 1 ? f1 : f2);
    const float* cen = mod == 0 ? c0 : (mod == 1 ? c1 : c2);
    int tid = threadIdx.x;
    int lane = tid & 31, w = tid >> 5;
    int g = lane >> 2, tig = lane & 3;

    __shared__ unsigned As[128 * ASTR];      // 18432 B
    __shared__ unsigned Bs[KCHUNK * BSTR];   // 3072 B

    int row0 = blockIdx.x * 128;

    // A loader: thread -> rows lr + p*32 (p=0..3), float4 col lc (32 floats)
    int lr = tid >> 3;
    int lc = (tid & 7) * 4;
    int bkk = lane;

    float nacc[4] = {0.f, 0.f, 0.f, 0.f};
    float cnacc0 = 0.f, cnacc1 = 0.f;
    float cfr[2][4];
#pragma unroll
    for (int t = 0; t < 2; t++)
#pragma unroll
        for (int i = 0; i < 4; i++) cfr[t][i] = 0.f;

    // prefetch chunk 0
    float4 ar[4];
    float br0, br1;
#pragma unroll
    for (int p = 0; p < 4; p++)
        ar[p] = *(const float4*)(fea + (size_t)(row0 + lr + p * 32) * D + kbase + lc);
    br0 = cen[(size_t)w * D + kbase + bkk];
    br1 = (w + 8 < KC) ? cen[(size_t)(w + 8) * D + kbase + bkk] : 0.f;

    for (int kb = 0; kb < DHALF; kb += KCHUNK) {
        // norms (fp32, exact) + cvt + stage
#pragma unroll
        for (int p = 0; p < 4; p++) {
            float4 v = ar[p];
            nacc[p] += v.x * v.x + v.y * v.y + v.z * v.z + v.w * v.w;
            unsigned* dst = &As[(lr + p * 32) * ASTR + lc];
            uint4 u;
            u.x = f2tf32(v.x); u.y = f2tf32(v.y); u.z = f2tf32(v.z); u.w = f2tf32(v.w);
            *(uint4*)dst = u;
        }
        cnacc0 += br0 * br0;
        cnacc1 += br1 * br1;
        Bs[bkk * BSTR + w]     = f2tf32(br0);
        Bs[bkk * BSTR + w + 8] = f2tf32(br1);
        __syncthreads();

        // prefetch next chunk
        if (kb + KCHUNK < DHALF) {
            int nb = kbase + kb + KCHUNK;
#pragma unroll
            for (int p = 0; p < 4; p++)
                ar[p] = *(const float4*)(fea + (size_t)(row0 + lr + p * 32) * D + nb + lc);
            br0 = cen[(size_t)w * D + nb + bkk];
            br1 = (w + 8 < KC) ? cen[(size_t)(w + 8) * D + nb + bkk] : 0.f;
        }

        // 4 k-steps of m16n8k8, two n-tiles
#pragma unroll
        for (int ks = 0; ks < KCHUNK; ks += 8) {
            unsigned a0 = As[(w * 16 + g) * ASTR + ks + tig];
            unsigned a1 = As[(w * 16 + g + 8) * ASTR + ks + tig];
            unsigned a2 = As[(w * 16 + g) * ASTR + ks + tig + 4];
            unsigned a3 = As[(w * 16 + g + 8) * ASTR + ks + tig + 4];
            unsigned b0 = Bs[(ks + tig) * BSTR + g];
            unsigned b1 = Bs[(ks + tig + 4) * BSTR + g];
            mma_tf32(cfr[0], a0, a1, a2, a3, b0, b1);
            unsigned b2 = Bs[(ks + tig) * BSTR + g + 8];
            unsigned b3 = Bs[(ks + tig + 4) * BSTR + g + 8];
            mma_tf32(cfr[1], a0, a1, a2, a3, b2, b3);
        }
        __syncthreads();
    }

    // partial row norms: 8 consecutive lanes share a row
#pragma unroll
    for (int p = 0; p < 4; p++) {
        float v = nacc[p];
        v += __shfl_xor_sync(0xffffffffu, v, 1);
        v += __shfl_xor_sync(0xffffffffu, v, 2);
        v += __shfl_xor_sync(0xffffffffu, v, 4);
        if ((tid & 7) == 0) g_pnrm[z][mod][row0 + lr + p * 32] = v;
    }
    // partial centroid norms (one block per (mod,z) stores)
    {
        float v0 = cnacc0, v1 = cnacc1;
#pragma unroll
        for (int o = 16; o > 0; o >>= 1) {
            v0 += __shfl_xor_sync(0xffffffffu, v0, o);
            v1 += __shfl_xor_sync(0xffffffffu, v1, o);
        }
        if (blockIdx.x == 0 && lane == 0) {
            g_pcn[z][mod][w]     = v0;
            g_pcn[z][mod][w + 8] = v1;
        }
    }
    // partial dots: raw fragment values (col 15 is zero-padded, ignored later)
    {
        int r_lo = row0 + w * 16 + g, r_hi = r_lo + 8;
#pragma unroll
        for (int t = 0; t < 2; t++) {
            int ca = t * 8 + 2 * tig, cb = ca + 1;
            g_pdot[z][mod][r_lo][ca] = cfr[t][0];
            g_pdot[z][mod][r_lo][cb] = cfr[t][1];
            g_pdot[z][mod][r_hi][ca] = cfr[t][2];
            g_pdot[z][mod][r_hi][cb] = cfr[t][3];
        }
    }
}

// ---------------- #5 (main): combine halves, avg + first-max argmax -------
__global__ __launch_bounds__(256) void sim_fin_kernel() {
    int mod = blockIdx.y;
    int tid = threadIdx.x;
    __shared__ float cninv[16];
    if (tid < 16)
        cninv[tid] = 1.f / fmaxf(sqrtf(g_pcn[0][mod][tid] + g_pcn[1][mod][tid]), 1e-12f);
    __syncthreads();

    int row = blockIdx.x * 256 + tid;
    float n = g_pnrm[0][mod][row] + g_pnrm[1][mod][row];
    float fin = 1.f / fmaxf(sqrtf(n), 1e-12f);
    const float* d0 = &g_pdot[0][mod][row][0];
    const float* d1 = &g_pdot[1][mod][row][0];
    float best = -1e30f; int bi = 0; float sum = 0.f;
#pragma unroll
    for (int k = 0; k < KC; k++) {
        float sim = (d0[k] + d1[k]) * fin * cninv[k];
        sum += sim;
        if (sim > best) { best = sim; bi = k; }
    }
    g_avg[mod][row] = sum * (1.0f / KC);
    g_assign[mod][row] = bi;
}

// ---------------- #6 (s2): radix select + attractive (smem-resident) ------
__global__ __launch_bounds__(1024) void select_attr_kernel(int rank0) {
    extern __shared__ unsigned int skeys[];       // 16384 u32 = 64 KB
    __shared__ unsigned int hist[256];
    __shared__ unsigned int sc[256];
    __shared__ unsigned int s_prefix;
    __shared__ int s_rank;
    __shared__ float s_thr;
    __shared__ float sred[32];

    int mod = blockIdx.x;
    const float* avg = g_avg[mod];
    int tid = threadIdx.x;
    int lane = tid & 31, warp = tid >> 5;

#pragma unroll
    for (int i = tid; i < B; i += 1024) {
        unsigned int u = __float_as_uint(avg[i]);
        skeys[i] = (u & 0x80000000u) ? ~u : (u | 0x80000000u);
    }
    if (tid == 0) { s_prefix = 0u; s_rank = rank0; }
    __syncthreads();

    for (int p = 3; p >= 0; p--) {
        if (tid < 256) hist[tid] = 0u;
        __syncthreads();
        unsigned int mask = (p == 3) ? 0u : (0xFFFFFFFFu << ((p + 1) * 8));
        unsigned int pref = s_prefix;
        int r = s_rank;
#pragma unroll
        for (int i = tid; i < B; i += 1024) {
            unsigned int u = skeys[i];
            if ((u & mask) == (pref & mask))
                atomicAdd(&hist[(u >> (p * 8)) & 255u], 1u);
        }
        __syncthreads();
        if (tid < 256) sc[tid] = hist[tid];
        __syncthreads();
#pragma unroll
        for (int off = 1; off < 256; off <<= 1) {
            unsigned int add = 0u;
            if (tid < 256 && tid >= off) add = sc[tid - off];
            __syncthreads();
            if (tid < 256) sc[tid] += add;
            __syncthreads();
        }
        if (tid < 256) {
            unsigned int inc = sc[tid], exc = inc - hist[tid];
            if ((unsigned int)r >= exc && (unsigned int)r < inc) {
                s_prefix = pref | ((unsigned int)tid << (p * 8));
                s_rank = r - (int)exc;
            }
        }
        __syncthreads();
    }
    if (tid == 0) {
        unsigned int u = s_prefix;
        unsigned int bits = (u & 0x80000000u) ? (u ^ 0x80000000u) : ~u;
        s_thr = __uint_as_float(bits);
    }
    __syncthreads();

    float thr = s_thr;
    float s = 0.f;
#pragma unroll
    for (int i = tid; i < B; i += 1024) {
        unsigned int u = skeys[i];
        unsigned int bits = (u & 0x80000000u) ? (u ^ 0x80000000u) : ~u;
        float a = __uint_as_float(bits);
        float w = 1.f / (1.f + expf(-5.0f * (a - thr)));   // ALPHA = 5
        s += w * (1.f - a);
    }
#pragma unroll
    for (int o = 16; o > 0; o >>= 1) s += __shfl_xor_sync(0xffffffffu, s, o);
    if (lane == 0) sred[warp] = s;
    __syncthreads();
    if (tid < 32) {
        float t = sred[tid];
#pragma unroll
        for (int o = 16; o > 0; o >>= 1) t += __shfl_xor_sync(0xffffffffu, t, o);
        if (tid == 0) g_attrpart[mod] = t;
    }
}

// ---------------- #7 (main): segment sums, 16-row unroll, L2 atomics ------
#define SEG_CHUNK 64
__global__ __launch_bounds__(256, 4) void seg_kernel(const float* __restrict__ outp) {
    __shared__ float acc[NMOD * KC * 256];   // 46080 B
    __shared__ int   s_a0[SEG_CHUNK], s_a1[SEG_CHUNK], s_a2[SEG_CHUNK];
    __shared__ float s_rm[SEG_CHUNK], s_ri[SEG_CHUNK];
    int tid = threadIdx.x;
    int c = blockIdx.x * 256 + tid;
    bool valid = c < C;
    for (int j = tid; j < NMOD * KC * 256; j += 256) acc[j] = 0.f;

    int r0 = blockIdx.y * SEG_ROWS;
    int rend = r0 + SEG_ROWS; if (rend > B) rend = B;

    for (int cb = r0; cb < rend; cb += SEG_CHUNK) {
        int clen = rend - cb; if (clen > SEG_CHUNK) clen = SEG_CHUNK;  // mult of 16
        __syncthreads();
        if (tid < clen) {
            s_a0[tid] = g_assign[0][cb + tid] * 256;
            s_a1[tid] = (KC + g_assign[1][cb + tid]) * 256;
            s_a2[tid] = (2 * KC + g_assign[2][cb + tid]) * 256;
            s_rm[tid] = g_rmax[cb + tid];
            s_ri[tid] = g_rinv[cb + tid];
        }
        __syncthreads();
        if (valid) {
            const float* op = outp + (size_t)cb * C + c;
            for (int rr = 0; rr < clen; rr += 16) {
                float p[16];
#pragma unroll
                for (int j = 0; j < 16; j++)
                    p[j] = op[(size_t)(rr + j) * C];           // 16 loads in flight
#pragma unroll
                for (int j = 0; j < 16; j++)
                    p[j] = __expf(p[j] - s_rm[rr + j]) * s_ri[rr + j];
#pragma unroll
                for (int j = 0; j < 16; j++) {
                    acc[s_a0[rr + j] + tid] += p[j];
                    acc[s_a1[rr + j] + tid] += p[j];
                    acc[s_a2[rr + j] + tid] += p[j];
                }
            }
        }
    }
    __syncthreads();
    if (valid) {
#pragma unroll
        for (int j = 0; j < NMOD * KC; j++)
            atomicAdd(&g_segsum[j][c], acc[j * 256 + tid]);
    }
}

// ---------------- #8 (main): entropy + counts + finalize (ticket) ---------
__global__ void entropy_final_kernel(float* dout_last) {
    int bk = blockIdx.x;  // 0..44
    int mod = bk / KC, k = bk % KC;
    int tid = threadIdx.x;

    int cnt = 0;
    const int* as = g_assign[mod];
    for (int i = tid; i < B; i += 256) cnt += (as[i] == k);
    __shared__ int ci[256];
    ci[tid] = cnt; __syncthreads();
    for (int o = 128; o > 0; o >>= 1) {
        if (tid < o) ci[tid] += ci[tid + o];
        __syncthreads();
    }
    float fcnt = (float)ci[0];
    float inv = 1.f / fmaxf(fcnt, 1.f);

    float s = 0.f;
    for (int i = tid; i < C; i += 256) {
        float mp = g_segsum[bk][i] * inv;
        s += mp * __logf(mp + 1e-8f);
    }
    __shared__ float sm[256];
    sm[tid] = s; __syncthreads();
    for (int o = 128; o > 0; o >>= 1) {
        if (tid < o) sm[tid] += sm[tid + o];
        __syncthreads();
    }
    if (tid == 0) {
        g_entpart[bk] = (fcnt >= 3.0f) ? sm[0] : 0.f;
        __threadfence();
        int t = atomicAdd(&g_ticket, 1);
        if (t == NMOD * KC - 1) {
            __threadfence();
            float div = 0.f;
#pragma unroll
            for (int j = 0; j < NMOD * KC; j++) div += g_entpart[j];
            float attr = g_attrpart[0] + g_attrpart[1] + g_attrpart[2];
            // LAM_CLUSTER = 6.0, LAM_DIV = 0.1
            *dout_last = 6.0f * (attr / (float)B) + 0.1f * div;
        }
    }
}

// ---------------- launch: fork-join multi-stream graph --------------------
extern "C" void kernel_launch(void* const* d_in, const int* in_sizes, int n_in,
                              void* d_out, int out_size) {
    const float* f0 = (const float*)d_in[0];
    const float* f1 = (const float*)d_in[1];
    const float* f2 = (const float*)d_in[2];
    const float* c0 = (const float*)d_in[3];
    const float* c1 = (const float*)d_in[4];
    const float* c2 = (const float*)d_in[5];
    const float* outp = (const float*)d_in[6];
    float* dout = (float*)d_out;
    (void)n_in; (void)in_sizes;

    static cudaStream_t s1 = 0, s2 = 0;
    static cudaEvent_t ev_root = 0, ev_stats = 0, ev_copy = 0, ev_sim = 0, ev_sel = 0;
    if (s1 == 0) {
        cudaStreamCreateWithFlags(&s1, cudaStreamNonBlocking);
        cudaStreamCreateWithFlags(&s2, cudaStreamNonBlocking);
        cudaEventCreateWithFlags(&ev_root, cudaEventDisableTiming);
        cudaEventCreateWithFlags(&ev_stats, cudaEventDisableTiming);
        cudaEventCreateWithFlags(&ev_copy, cudaEventDisableTiming);
        cudaEventCreateWithFlags(&ev_sim, cudaEventDisableTiming);
        cudaEventCreateWithFlags(&ev_sel, cudaEventDisableTiming);
        cudaFuncSetAttribute(select_attr_kernel,
                             cudaFuncAttributeMaxDynamicSharedMemorySize, B * 4);
    }

    // fork to s1: init + stats + copy (independent of sim)
    cudaEventRecord(ev_root, 0);
    cudaStreamWaitEvent(s1, ev_root, 0);
    init_kernel<<<(NMOD * KC * C + 255) / 256, 256, 0, s1>>>();             // #1
    stats_kernel<<<B / 8, 256, 0, s1>>>(outp);                              // #2
    cudaEventRecord(ev_stats, s1);
    copy_kernel<<<2048, 256, 0, s1>>>(outp, dout);                          // #3
    cudaEventRecord(ev_copy, s1);

    // main: K-split sim (profiled slot #4) + finalize
    sim_kernel<<<dim3(B / 128, NMOD, 2), 256>>>(f0, f1, f2, c0, c1, c2);    // #4
    sim_fin_kernel<<<dim3(B / 256, NMOD), 256>>>();                         // #5

    // fork to s2: select (depends on sim_fin)
    cudaEventRecord(ev_sim, 0);
    cudaStreamWaitEvent(s2, ev_sim, 0);
    int rank0 = B - (int)((double)B * 0.6);   // = 6554
    select_attr_kernel<<<NMOD, 1024, B * 4, s2>>>(rank0);                   // #6
    cudaEventRecord(ev_sel, s2);

    // main: seg needs stats(+init) + assigns(sim_fin, same stream)
    cudaStreamWaitEvent(0, ev_stats, 0);
    seg_kernel<<<dim3(4, 148), 256>>>(outp);                                // #7

    // join select + copy, then entropy+finalize
    cudaStreamWaitEvent(0, ev_sel, 0);
    cudaStreamWaitEvent(0, ev_copy, 0);
    entropy_final_kernel<<<NMOD * KC, 256>>>(dout + (size_t)out_size - 1);  // #8
}

// round 14
// speedup vs baseline: 1.1011x; 1.0614x over previous
#include <cuda_runtime.h>
#include <math.h>

#define B    16384
#define D    1024
#define KC   15
#define C    1000
#define NMOD 3

#define SEG_ROWS 112   // grid (4,148): 148*112 = 16576 >= B

// ---------------- scratch (device globals; no allocation) ----------------
__device__ float g_avg[NMOD][B];
__device__ int   g_assign[NMOD][B];
__device__ float g_rmax[B];
__device__ float g_rinv[B];
__device__ float g_segsum[NMOD * KC][C];   // 180 KB, L2-resident
__device__ float g_entpart[NMOD * KC];
__device__ float g_attrpart[NMOD];
__device__ int   g_ticket;

__device__ __forceinline__ unsigned f2tf32(float x) {
    unsigned r; asm("cvt.rna.tf32.f32 %0, %1;" : "=r"(r) : "f"(x)); return r;
}
__device__ __forceinline__ void mma_tf32(float c[4], unsigned a0, unsigned a1,
                                         unsigned a2, unsigned a3,
                                         unsigned b0, unsigned b1) {
    asm volatile(
        "mma.sync.aligned.m16n8k8.row.col.f32.tf32.tf32.f32 "
        "{%0,%1,%2,%3}, {%4,%5,%6,%7}, {%8,%9}, {%0,%1,%2,%3};\n"
        : "+f"(c[0]), "+f"(c[1]), "+f"(c[2]), "+f"(c[3])
        : "r"(a0), "r"(a1), "r"(a2), "r"(a3), "r"(b0), "r"(b1));
}

// ---------------- #1 (s1): zero segsum + ticket ----------------
__global__ void init_kernel() {
    int i = blockIdx.x * blockDim.x + threadIdx.x;
    if (i < NMOD * KC * C) ((float*)g_segsum)[i] = 0.f;
    if (i == 0) g_ticket = 0;
}

// ---------------- #2 (s1): softmax stats only ----------------
__global__ __launch_bounds__(256) void stats_kernel(const float* __restrict__ outp) {
    int warp = threadIdx.x >> 5, lane = threadIdx.x & 31;
    int row = blockIdx.x * 8 + warp;
    const float4* r4 = (const float4*)(outp + (size_t)row * C);
    float4 a[8];
    float m = -INFINITY;
#pragma unroll
    for (int i = 0; i < 8; i++) {
        int j = lane + i * 32;
        if (j < C / 4) {
            float4 x = r4[j]; a[i] = x;
            m = fmaxf(m, fmaxf(fmaxf(x.x, x.y), fmaxf(x.z, x.w)));
        }
    }
#pragma unroll
    for (int o = 16; o > 0; o >>= 1) m = fmaxf(m, __shfl_xor_sync(0xffffffffu, m, o));
    float s = 0.f;
#pragma unroll
    for (int i = 0; i < 8; i++) {
        int j = lane + i * 32;
        if (j < C / 4)
            s += __expf(a[i].x - m) + __expf(a[i].y - m) + __expf(a[i].z - m) + __expf(a[i].w - m);
    }
#pragma unroll
    for (int o = 16; o > 0; o >>= 1) s += __shfl_xor_sync(0xffffffffu, s, o);
    if (lane == 0) { g_rmax[row] = m; g_rinv[row] = 1.f / s; }
}

// ---------------- #3 (main): similarities via tf32 MMA (R11 exact) --------
// 128 rows/block, grid (128, 3). KCHUNK=64: 8 float4 prefetch regs in flight.
#define KCHUNK  64
#define ASTR    68   // 68 mod 32 == 4: conflict-free frag LDS (banks 4g+tig)
#define BSTR    24
__global__ __launch_bounds__(256) void sim_kernel(
    const float* __restrict__ f0, const float* __restrict__ f1, const float* __restrict__ f2,
    const float* __restrict__ c0, const float* __restrict__ c1, const float* __restrict__ c2) {
    int mod = blockIdx.y;
    const float* fea = mod == 0 ? f0 : (mod == 1 ? f1 : f2);
    const float* cen = mod == 0 ? c0 : (mod == 1 ? c1 : c2);
    int tid = threadIdx.x;
    int lane = tid & 31, w = tid >> 5;
    int g = lane >> 2, tig = lane & 3;

    __shared__ unsigned As[128 * ASTR];      // 34816 B
    __shared__ unsigned Bs[KCHUNK * BSTR];   // 6144 B
    __shared__ float nrm_s[128];
    __shared__ float cns[16];
    __shared__ float cninv[16];

    int row0 = blockIdx.x * 128;

    int lr = tid >> 4;
    int lc = (tid & 15) * 4;
    int bkk = lane;

    float nacc[8] = {0.f, 0.f, 0.f, 0.f, 0.f, 0.f, 0.f, 0.f};
    float cnacc0 = 0.f, cnacc1 = 0.f;
    float cfr[2][4];
#pragma unroll
    for (int t = 0; t < 2; t++)
#pragma unroll
        for (int i = 0; i < 4; i++) cfr[t][i] = 0.f;

    float4 ar[8];
    float br0a, br0b, br1a, br1b;
#pragma unroll
    for (int p = 0; p < 8; p++)
        ar[p] = *(const float4*)(fea + (size_t)(row0 + lr + p * 16) * D + lc);
    br0a = cen[(size_t)w * D + bkk];
    br0b = cen[(size_t)w * D + bkk + 32];
    br1a = (w + 8 < KC) ? cen[(size_t)(w + 8) * D + bkk] : 0.f;
    br1b = (w + 8 < KC) ? cen[(size_t)(w + 8) * D + bkk + 32] : 0.f;

    for (int kb = 0; kb < D; kb += KCHUNK) {
#pragma unroll
        for (int p = 0; p < 8; p++) {
            float4 v = ar[p];
            nacc[p] += v.x * v.x + v.y * v.y + v.z * v.z + v.w * v.w;
            unsigned* dst = &As[(lr + p * 16) * ASTR + lc];
            uint4 u;
            u.x = f2tf32(v.x); u.y = f2tf32(v.y); u.z = f2tf32(v.z); u.w = f2tf32(v.w);
            *(uint4*)dst = u;
        }
        cnacc0 += br0a * br0a + br0b * br0b;
        cnacc1 += br1a * br1a + br1b * br1b;
        Bs[bkk * BSTR + w]            = f2tf32(br0a);
        Bs[(bkk + 32) * BSTR + w]     = f2tf32(br0b);
        Bs[bkk * BSTR + w + 8]        = f2tf32(br1a);
        Bs[(bkk + 32) * BSTR + w + 8] = f2tf32(br1b);
        __syncthreads();

        if (kb + KCHUNK < D) {
            int nb = kb + KCHUNK;
#pragma unroll
            for (int p = 0; p < 8; p++)
                ar[p] = *(const float4*)(fea + (size_t)(row0 + lr + p * 16) * D + nb + lc);
            br0a = cen[(size_t)w * D + nb + bkk];
            br0b = cen[(size_t)w * D + nb + bkk + 32];
            br1a = (w + 8 < KC) ? cen[(size_t)(w + 8) * D + nb + bkk] : 0.f;
            br1b = (w + 8 < KC) ? cen[(size_t)(w + 8) * D + nb + bkk + 32] : 0.f;
        }

#pragma unroll
        for (int ks = 0; ks < KCHUNK; ks += 8) {
            unsigned a0 = As[(w * 16 + g) * ASTR + ks + tig];
            unsigned a1 = As[(w * 16 + g + 8) * ASTR + ks + tig];
            unsigned a2 = As[(w * 16 + g) * ASTR + ks + tig + 4];
            unsigned a3 = As[(w * 16 + g + 8) * ASTR + ks + tig + 4];
            unsigned b0 = Bs[(ks + tig) * BSTR + g];
            unsigned b1 = Bs[(ks + tig + 4) * BSTR + g];
            mma_tf32(cfr[0], a0, a1, a2, a3, b0, b1);
            unsigned b2 = Bs[(ks + tig) * BSTR + g + 8];
            unsigned b3 = Bs[(ks + tig + 4) * BSTR + g + 8];
            mma_tf32(cfr[1], a0, a1, a2, a3, b2, b3);
        }
        __syncthreads();
    }

#pragma unroll
    for (int p = 0; p < 8; p++) {
        float v = nacc[p];
        v += __shfl_xor_sync(0xffffffffu, v, 1);
        v += __shfl_xor_sync(0xffffffffu, v, 2);
        v += __shfl_xor_sync(0xffffffffu, v, 4);
        v += __shfl_xor_sync(0xffffffffu, v, 8);
        if ((tid & 15) == 0) nrm_s[lr + p * 16] = v;
    }
    float v0 = cnacc0, v1 = cnacc1;
#pragma unroll
    for (int o = 16; o > 0; o >>= 1) {
        v0 += __shfl_xor_sync(0xffffffffu, v0, o);
        v1 += __shfl_xor_sync(0xffffffffu, v1, o);
    }
    if (lane == 0) { cns[w] = v0; cns[w + 8] = v1; }
    __syncthreads();
    if (tid < 16) cninv[tid] = 1.f / fmaxf(sqrtf(cns[tid]), 1e-12f);
    __syncthreads();

    int r_lo = w * 16 + g, r_hi = r_lo + 8;
    float fin_lo = 1.f / fmaxf(sqrtf(nrm_s[r_lo]), 1e-12f);
    float fin_hi = 1.f / fmaxf(sqrtf(nrm_s[r_hi]), 1e-12f);

    float sum_lo = 0.f, sum_hi = 0.f;
    float mx_lo = -1e30f, mx_hi = -1e30f;
    int ai_lo = 0, ai_hi = 0;
#pragma unroll
    for (int t = 0; t < 2; t++) {
        int ca = t * 8 + 2 * tig, cb = ca + 1;
        {
            float s_lo = cfr[t][0] * fin_lo * cninv[ca];
            float s_hi = cfr[t][2] * fin_hi * cninv[ca];
            sum_lo += s_lo; sum_hi += s_hi;
            if (s_lo > mx_lo) { mx_lo = s_lo; ai_lo = ca; }
            if (s_hi > mx_hi) { mx_hi = s_hi; ai_hi = ca; }
        }
        if (cb < KC) {
            float s_lo = cfr[t][1] * fin_lo * cninv[cb];
            float s_hi = cfr[t][3] * fin_hi * cninv[cb];
            sum_lo += s_lo; sum_hi += s_hi;
            if (s_lo > mx_lo) { mx_lo = s_lo; ai_lo = cb; }
            if (s_hi > mx_hi) { mx_hi = s_hi; ai_hi = cb; }
        }
    }
#pragma unroll
    for (int o = 1; o < 4; o <<= 1) {
        sum_lo += __shfl_xor_sync(0xffffffffu, sum_lo, o);
        sum_hi += __shfl_xor_sync(0xffffffffu, sum_hi, o);
        float om_lo = __shfl_xor_sync(0xffffffffu, mx_lo, o);
        int   oa_lo = __shfl_xor_sync(0xffffffffu, ai_lo, o);
        float om_hi = __shfl_xor_sync(0xffffffffu, mx_hi, o);
        int   oa_hi = __shfl_xor_sync(0xffffffffu, ai_hi, o);
        if (om_lo > mx_lo || (om_lo == mx_lo && oa_lo < ai_lo)) { mx_lo = om_lo; ai_lo = oa_lo; }
        if (om_hi > mx_hi || (om_hi == mx_hi && oa_hi < ai_hi)) { mx_hi = om_hi; ai_hi = oa_hi; }
    }
    if (tig == 0) {
        g_avg[mod][row0 + r_lo] = sum_lo * (1.0f / KC);
        g_assign[mod][row0 + r_lo] = ai_lo;
        g_avg[mod][row0 + r_hi] = sum_hi * (1.0f / KC);
        g_assign[mod][row0 + r_hi] = ai_hi;
    }
}

// ---------------- #4 (main, PROFILED): segment sums, 16-row unroll --------
#define SEG_CHUNK 64
__global__ __launch_bounds__(256, 4) void seg_kernel(const float* __restrict__ outp) {
    __shared__ float acc[NMOD * KC * 256];   // 46080 B
    __shared__ int   s_a0[SEG_CHUNK], s_a1[SEG_CHUNK], s_a2[SEG_CHUNK];
    __shared__ float s_rm[SEG_CHUNK], s_ri[SEG_CHUNK];
    int tid = threadIdx.x;
    int c = blockIdx.x * 256 + tid;
    bool valid = c < C;
    for (int j = tid; j < NMOD * KC * 256; j += 256) acc[j] = 0.f;

    int r0 = blockIdx.y * SEG_ROWS;
    int rend = r0 + SEG_ROWS; if (rend > B) rend = B;

    for (int cb = r0; cb < rend; cb += SEG_CHUNK) {
        int clen = rend - cb; if (clen > SEG_CHUNK) clen = SEG_CHUNK;  // mult of 16
        __syncthreads();
        if (tid < clen) {
            s_a0[tid] = g_assign[0][cb + tid] * 256;
            s_a1[tid] = (KC + g_assign[1][cb + tid]) * 256;
            s_a2[tid] = (2 * KC + g_assign[2][cb + tid]) * 256;
            s_rm[tid] = g_rmax[cb + tid];
            s_ri[tid] = g_rinv[cb + tid];
        }
        __syncthreads();
        if (valid) {
            const float* op = outp + (size_t)cb * C + c;
            for (int rr = 0; rr < clen; rr += 16) {
                float p[16];
#pragma unroll
                for (int j = 0; j < 16; j++)
                    p[j] = op[(size_t)(rr + j) * C];           // 16 loads in flight
#pragma unroll
                for (int j = 0; j < 16; j++)
                    p[j] = __expf(p[j] - s_rm[rr + j]) * s_ri[rr + j];
#pragma unroll
                for (int j = 0; j < 16; j++) {
                    acc[s_a0[rr + j] + tid] += p[j];
                    acc[s_a1[rr + j] + tid] += p[j];
                    acc[s_a2[rr + j] + tid] += p[j];
                }
            }
        }
    }
    __syncthreads();
    if (valid) {
#pragma unroll
        for (int j = 0; j < NMOD * KC; j++)
            atomicAdd(&g_segsum[j][c], acc[j * 256 + tid]);
    }
}

// ---------------- #5 (s2): radix select + attractive (smem-resident) ------
__global__ __launch_bounds__(1024) void select_attr_kernel(int rank0) {
    extern __shared__ unsigned int skeys[];       // 16384 u32 = 64 KB
    __shared__ unsigned int hist[256];
    __shared__ unsigned int sc[256];
    __shared__ unsigned int s_prefix;
    __shared__ int s_rank;
    __shared__ float s_thr;
    __shared__ float sred[32];

    int mod = blockIdx.x;
    const float* avg = g_avg[mod];
    int tid = threadIdx.x;
    int lane = tid & 31, warp = tid >> 5;

#pragma unroll
    for (int i = tid; i < B; i += 1024) {
        unsigned int u = __float_as_uint(avg[i]);
        skeys[i] = (u & 0x80000000u) ? ~u : (u | 0x80000000u);
    }
    if (tid == 0) { s_prefix = 0u; s_rank = rank0; }
    __syncthreads();

    for (int p = 3; p >= 0; p--) {
        if (tid < 256) hist[tid] = 0u;
        __syncthreads();
        unsigned int mask = (p == 3) ? 0u : (0xFFFFFFFFu << ((p + 1) * 8));
        unsigned int pref = s_prefix;
        int r = s_rank;
#pragma unroll
        for (int i = tid; i < B; i += 1024) {
            unsigned int u = skeys[i];
            if ((u & mask) == (pref & mask))
                atomicAdd(&hist[(u >> (p * 8)) & 255u], 1u);
        }
        __syncthreads();
        if (tid < 256) sc[tid] = hist[tid];
        __syncthreads();
#pragma unroll
        for (int off = 1; off < 256; off <<= 1) {
            unsigned int add = 0u;
            if (tid < 256 && tid >= off) add = sc[tid - off];
            __syncthreads();
            if (tid < 256) sc[tid] += add;
            __syncthreads();
        }
        if (tid < 256) {
            unsigned int inc = sc[tid], exc = inc - hist[tid];
            if ((unsigned int)r >= exc && (unsigned int)r < inc) {
                s_prefix = pref | ((unsigned int)tid << (p * 8));
                s_rank = r - (int)exc;
            }
        }
        __syncthreads();
    }
    if (tid == 0) {
        unsigned int u = s_prefix;
        unsigned int bits = (u & 0x80000000u) ? (u ^ 0x80000000u) : ~u;
        s_thr = __uint_as_float(bits);
    }
    __syncthreads();

    float thr = s_thr;
    float s = 0.f;
#pragma unroll
    for (int i = tid; i < B; i += 1024) {
        unsigned int u = skeys[i];
        unsigned int bits = (u & 0x80000000u) ? (u ^ 0x80000000u) : ~u;
        float a = __uint_as_float(bits);
        float w = 1.f / (1.f + expf(-5.0f * (a - thr)));   // ALPHA = 5
        s += w * (1.f - a);
    }
#pragma unroll
    for (int o = 16; o > 0; o >>= 1) s += __shfl_xor_sync(0xffffffffu, s, o);
    if (lane == 0) sred[warp] = s;
    __syncthreads();
    if (tid < 32) {
        float t = sred[tid];
#pragma unroll
        for (int o = 16; o > 0; o >>= 1) t += __shfl_xor_sync(0xffffffffu, t, o);
        if (tid == 0) g_attrpart[mod] = t;
    }
}

// ---------------- #6 (s1): pure copy out -> d_out (overlaps seg) ----------
__global__ __launch_bounds__(256) void copy_kernel(const float* __restrict__ src,
                                                   float* __restrict__ dst) {
    size_t i = (size_t)blockIdx.x * 256 + threadIdx.x;
    size_t n4 = (size_t)B * C / 4;
    const float4* s4 = (const float4*)src;
    float4* d4 = (float4*)dst;
    for (; i < n4; i += (size_t)gridDim.x * 256) d4[i] = s4[i];
}

// ---------------- #7 (main): entropy + counts + finalize (ticket) ---------
__global__ void entropy_final_kernel(float* dout_last) {
    int bk = blockIdx.x;  // 0..44
    int mod = bk / KC, k = bk % KC;
    int tid = threadIdx.x;

    int cnt = 0;
    const int* as = g_assign[mod];
    for (int i = tid; i < B; i += 256) cnt += (as[i] == k);
    __shared__ int ci[256];
    ci[tid] = cnt; __syncthreads();
    for (int o = 128; o > 0; o >>= 1) {
        if (tid < o) ci[tid] += ci[tid + o];
        __syncthreads();
    }
    float fcnt = (float)ci[0];
    float inv = 1.f / fmaxf(fcnt, 1.f);

    float s = 0.f;
    for (int i = tid; i < C; i += 256) {
        float mp = g_segsum[bk][i] * inv;
        s += mp * __logf(mp + 1e-8f);
    }
    __shared__ float sm[256];
    sm[tid] = s; __syncthreads();
    for (int o = 128; o > 0; o >>= 1) {
        if (tid < o) sm[tid] += sm[tid + o];
        __syncthreads();
    }
    if (tid == 0) {
        g_entpart[bk] = (fcnt >= 3.0f) ? sm[0] : 0.f;
        __threadfence();
        int t = atomicAdd(&g_ticket, 1);
        if (t == NMOD * KC - 1) {
            __threadfence();
            float div = 0.f;
#pragma unroll
            for (int j = 0; j < NMOD * KC; j++) div += g_entpart[j];
            float attr = g_attrpart[0] + g_attrpart[1] + g_attrpart[2];
            // LAM_CLUSTER = 6.0, LAM_DIV = 0.1
            *dout_last = 6.0f * (attr / (float)B) + 0.1f * div;
        }
    }
}

// ---------------- launch: copy moved off sim's shadow ---------------------
extern "C" void kernel_launch(void* const* d_in, const int* in_sizes, int n_in,
                              void* d_out, int out_size) {
    const float* f0 = (const float*)d_in[0];
    const float* f1 = (const float*)d_in[1];
    const float* f2 = (const float*)d_in[2];
    const float* c0 = (const float*)d_in[3];
    const float* c1 = (const float*)d_in[4];
    const float* c2 = (const float*)d_in[5];
    const float* outp = (const float*)d_in[6];
    float* dout = (float*)d_out;
    (void)n_in; (void)in_sizes;

    static cudaStream_t s1 = 0, s2 = 0;
    static cudaEvent_t ev_root = 0, ev_stats = 0, ev_copy = 0, ev_sim = 0, ev_sel = 0;
    if (s1 == 0) {
        cudaStreamCreateWithFlags(&s1, cudaStreamNonBlocking);
        cudaStreamCreateWithFlags(&s2, cudaStreamNonBlocking);
        cudaEventCreateWithFlags(&ev_root, cudaEventDisableTiming);
        cudaEventCreateWithFlags(&ev_stats, cudaEventDisableTiming);
        cudaEventCreateWithFlags(&ev_copy, cudaEventDisableTiming);
        cudaEventCreateWithFlags(&ev_sim, cudaEventDisableTiming);
        cudaEventCreateWithFlags(&ev_sel, cudaEventDisableTiming);
        cudaFuncSetAttribute(select_attr_kernel,
                             cudaFuncAttributeMaxDynamicSharedMemorySize, B * 4);
    }

    // fork to s1: init + stats only (light; minimal contention with sim)
    cudaEventRecord(ev_root, 0);
    cudaStreamWaitEvent(s1, ev_root, 0);
    init_kernel<<<(NMOD * KC * C + 255) / 256, 256, 0, s1>>>();             // #1
    stats_kernel<<<B / 8, 256, 0, s1>>>(outp);                              // #2
    cudaEventRecord(ev_stats, s1);

    // main: sim (R11 exact)
    sim_kernel<<<dim3(B / 128, NMOD), 256>>>(f0, f1, f2, c0, c1, c2);       // #3
    cudaEventRecord(ev_sim, 0);

    // main: seg (profiled slot #4) — needs stats + assigns
    cudaStreamWaitEvent(0, ev_stats, 0);
    seg_kernel<<<dim3(4, 148), 256>>>(outp);                                // #4

    // fork to s2: select (depends only on sim); overlaps seg
    cudaStreamWaitEvent(s2, ev_sim, 0);
    int rank0 = B - (int)((double)B * 0.6);   // = 6554
    select_attr_kernel<<<NMOD, 1024, B * 4, s2>>>(rank0);                   // #5
    cudaEventRecord(ev_sel, s2);

    // fork to s1: copy AFTER sim — overlaps seg (BW headroom), not sim
    cudaStreamWaitEvent(s1, ev_sim, 0);
    copy_kernel<<<2048, 256, 0, s1>>>(outp, dout);                          // #6
    cudaEventRecord(ev_copy, s1);

    // join select + copy, then entropy+finalize
    cudaStreamWaitEvent(0, ev_sel, 0);
    cudaStreamWaitEvent(0, ev_copy, 0);
    entropy_final_kernel<<<NMOD * KC, 256>>>(dout + (size_t)out_size - 1);  // #7
}

// round 15
// speedup vs baseline: 1.3256x; 1.2039x over previous
#include <cuda_runtime.h>
#include <math.h>

#define B    16384
#define D    1024
#define KC   15
#define C    1000
#define NMOD 3

#define SEG_ROWS 112   // grid (4,148): 148*112 = 16576 >= B

// ---------------- scratch (device globals; no allocation) ----------------
__device__ float g_avg[NMOD][B];
__device__ int   g_assign[NMOD][B];
__device__ float g_rmax[B];
__device__ float g_rinv[B];
__device__ float g_segsum[NMOD * KC][C];   // 180 KB, L2-resident
__device__ float g_entpart[NMOD * KC];
__device__ float g_attrpart[NMOD];
__device__ int   g_ticket;

__device__ __forceinline__ unsigned f2tf32(float x) {
    unsigned r; asm("cvt.rna.tf32.f32 %0, %1;" : "=r"(r) : "f"(x)); return r;
}
__device__ __forceinline__ void mma_tf32(float c[4], unsigned a0, unsigned a1,
                                         unsigned a2, unsigned a3,
                                         unsigned b0, unsigned b1) {
    asm volatile(
        "mma.sync.aligned.m16n8k8.row.col.f32.tf32.tf32.f32 "
        "{%0,%1,%2,%3}, {%4,%5,%6,%7}, {%8,%9}, {%0,%1,%2,%3};\n"
        : "+f"(c[0]), "+f"(c[1]), "+f"(c[2]), "+f"(c[3])
        : "r"(a0), "r"(a1), "r"(a2), "r"(a3), "r"(b0), "r"(b1));
}

// ---------------- init: zero segsum + ticket (s1) ----------------
__global__ void init_kernel() {
    int i = blockIdx.x * blockDim.x + threadIdx.x;
    if (i < NMOD * KC * C) ((float*)g_segsum)[i] = 0.f;
    if (i == 0) g_ticket = 0;
}

// ---------------- softmax stats only (s1) ----------------
__global__ __launch_bounds__(256) void stats_kernel(const float* __restrict__ outp) {
    int warp = threadIdx.x >> 5, lane = threadIdx.x & 31;
    int row = blockIdx.x * 8 + warp;
    const float4* r4 = (const float4*)(outp + (size_t)row * C);
    float4 a[8];
    float m = -INFINITY;
#pragma unroll
    for (int i = 0; i < 8; i++) {
        int j = lane + i * 32;
        if (j < C / 4) {
            float4 x = r4[j]; a[i] = x;
            m = fmaxf(m, fmaxf(fmaxf(x.x, x.y), fmaxf(x.z, x.w)));
        }
    }
#pragma unroll
    for (int o = 16; o > 0; o >>= 1) m = fmaxf(m, __shfl_xor_sync(0xffffffffu, m, o));
    float s = 0.f;
#pragma unroll
    for (int i = 0; i < 8; i++) {
        int j = lane + i * 32;
        if (j < C / 4)
            s += __expf(a[i].x - m) + __expf(a[i].y - m) + __expf(a[i].z - m) + __expf(a[i].w - m);
    }
#pragma unroll
    for (int o = 16; o > 0; o >>= 1) s += __shfl_xor_sync(0xffffffffu, s, o);
    if (lane == 0) { g_rmax[row] = m; g_rinv[row] = 1.f / s; }
}

// ---------------- similarities via tf32 MMA (R11 exact, main) -------------
#define KCHUNK  64
#define ASTR    68
#define BSTR    24
__global__ __launch_bounds__(256) void sim_kernel(
    const float* __restrict__ f0, const float* __restrict__ f1, const float* __restrict__ f2,
    const float* __restrict__ c0, const float* __restrict__ c1, const float* __restrict__ c2) {
    int mod = blockIdx.y;
    const float* fea = mod == 0 ? f0 : (mod == 1 ? f1 : f2);
    const float* cen = mod == 0 ? c0 : (mod == 1 ? c1 : c2);
    int tid = threadIdx.x;
    int lane = tid & 31, w = tid >> 5;
    int g = lane >> 2, tig = lane & 3;

    __shared__ unsigned As[128 * ASTR];
    __shared__ unsigned Bs[KCHUNK * BSTR];
    __shared__ float nrm_s[128];
    __shared__ float cns[16];
    __shared__ float cninv[16];

    int row0 = blockIdx.x * 128;
    int lr = tid >> 4;
    int lc = (tid & 15) * 4;
    int bkk = lane;

    float nacc[8] = {0.f, 0.f, 0.f, 0.f, 0.f, 0.f, 0.f, 0.f};
    float cnacc0 = 0.f, cnacc1 = 0.f;
    float cfr[2][4];
#pragma unroll
    for (int t = 0; t < 2; t++)
#pragma unroll
        for (int i = 0; i < 4; i++) cfr[t][i] = 0.f;

    float4 ar[8];
    float br0a, br0b, br1a, br1b;
#pragma unroll
    for (int p = 0; p < 8; p++)
        ar[p] = *(const float4*)(fea + (size_t)(row0 + lr + p * 16) * D + lc);
    br0a = cen[(size_t)w * D + bkk];
    br0b = cen[(size_t)w * D + bkk + 32];
    br1a = (w + 8 < KC) ? cen[(size_t)(w + 8) * D + bkk] : 0.f;
    br1b = (w + 8 < KC) ? cen[(size_t)(w + 8) * D + bkk + 32] : 0.f;

    for (int kb = 0; kb < D; kb += KCHUNK) {
#pragma unroll
        for (int p = 0; p < 8; p++) {
            float4 v = ar[p];
            nacc[p] += v.x * v.x + v.y * v.y + v.z * v.z + v.w * v.w;
            unsigned* dst = &As[(lr + p * 16) * ASTR + lc];
            uint4 u;
            u.x = f2tf32(v.x); u.y = f2tf32(v.y); u.z = f2tf32(v.z); u.w = f2tf32(v.w);
            *(uint4*)dst = u;
        }
        cnacc0 += br0a * br0a + br0b * br0b;
        cnacc1 += br1a * br1a + br1b * br1b;
        Bs[bkk * BSTR + w]            = f2tf32(br0a);
        Bs[(bkk + 32) * BSTR + w]     = f2tf32(br0b);
        Bs[bkk * BSTR + w + 8]        = f2tf32(br1a);
        Bs[(bkk + 32) * BSTR + w + 8] = f2tf32(br1b);
        __syncthreads();

        if (kb + KCHUNK < D) {
            int nb = kb + KCHUNK;
#pragma unroll
            for (int p = 0; p < 8; p++)
                ar[p] = *(const float4*)(fea + (size_t)(row0 + lr + p * 16) * D + nb + lc);
            br0a = cen[(size_t)w * D + nb + bkk];
            br0b = cen[(size_t)w * D + nb + bkk + 32];
            br1a = (w + 8 < KC) ? cen[(size_t)(w + 8) * D + nb + bkk] : 0.f;
            br1b = (w + 8 < KC) ? cen[(size_t)(w + 8) * D + nb + bkk + 32] : 0.f;
        }

#pragma unroll
        for (int ks = 0; ks < KCHUNK; ks += 8) {
            unsigned a0 = As[(w * 16 + g) * ASTR + ks + tig];
            unsigned a1 = As[(w * 16 + g + 8) * ASTR + ks + tig];
            unsigned a2 = As[(w * 16 + g) * ASTR + ks + tig + 4];
            unsigned a3 = As[(w * 16 + g + 8) * ASTR + ks + tig + 4];
            unsigned b0 = Bs[(ks + tig) * BSTR + g];
            unsigned b1 = Bs[(ks + tig + 4) * BSTR + g];
            mma_tf32(cfr[0], a0, a1, a2, a3, b0, b1);
            unsigned b2 = Bs[(ks + tig) * BSTR + g + 8];
            unsigned b3 = Bs[(ks + tig + 4) * BSTR + g + 8];
            mma_tf32(cfr[1], a0, a1, a2, a3, b2, b3);
        }
        __syncthreads();
    }

#pragma unroll
    for (int p = 0; p < 8; p++) {
        float v = nacc[p];
        v += __shfl_xor_sync(0xffffffffu, v, 1);
        v += __shfl_xor_sync(0xffffffffu, v, 2);
        v += __shfl_xor_sync(0xffffffffu, v, 4);
        v += __shfl_xor_sync(0xffffffffu, v, 8);
        if ((tid & 15) == 0) nrm_s[lr + p * 16] = v;
    }
    float v0 = cnacc0, v1 = cnacc1;
#pragma unroll
    for (int o = 16; o > 0; o >>= 1) {
        v0 += __shfl_xor_sync(0xffffffffu, v0, o);
        v1 += __shfl_xor_sync(0xffffffffu, v1, o);
    }
    if (lane == 0) { cns[w] = v0; cns[w + 8] = v1; }
    __syncthreads();
    if (tid < 16) cninv[tid] = 1.f / fmaxf(sqrtf(cns[tid]), 1e-12f);
    __syncthreads();

    int r_lo = w * 16 + g, r_hi = r_lo + 8;
    float fin_lo = 1.f / fmaxf(sqrtf(nrm_s[r_lo]), 1e-12f);
    float fin_hi = 1.f / fmaxf(sqrtf(nrm_s[r_hi]), 1e-12f);

    float sum_lo = 0.f, sum_hi = 0.f;
    float mx_lo = -1e30f, mx_hi = -1e30f;
    int ai_lo = 0, ai_hi = 0;
#pragma unroll
    for (int t = 0; t < 2; t++) {
        int ca = t * 8 + 2 * tig, cb = ca + 1;
        {
            float s_lo = cfr[t][0] * fin_lo * cninv[ca];
            float s_hi = cfr[t][2] * fin_hi * cninv[ca];
            sum_lo += s_lo; sum_hi += s_hi;
            if (s_lo > mx_lo) { mx_lo = s_lo; ai_lo = ca; }
            if (s_hi > mx_hi) { mx_hi = s_hi; ai_hi = ca; }
        }
        if (cb < KC) {
            float s_lo = cfr[t][1] * fin_lo * cninv[cb];
            float s_hi = cfr[t][3] * fin_hi * cninv[cb];
            sum_lo += s_lo; sum_hi += s_hi;
            if (s_lo > mx_lo) { mx_lo = s_lo; ai_lo = cb; }
            if (s_hi > mx_hi) { mx_hi = s_hi; ai_hi = cb; }
        }
    }
#pragma unroll
    for (int o = 1; o < 4; o <<= 1) {
        sum_lo += __shfl_xor_sync(0xffffffffu, sum_lo, o);
        sum_hi += __shfl_xor_sync(0xffffffffu, sum_hi, o);
        float om_lo = __shfl_xor_sync(0xffffffffu, mx_lo, o);
        int   oa_lo = __shfl_xor_sync(0xffffffffu, ai_lo, o);
        float om_hi = __shfl_xor_sync(0xffffffffu, mx_hi, o);
        int   oa_hi = __shfl_xor_sync(0xffffffffu, ai_hi, o);
        if (om_lo > mx_lo || (om_lo == mx_lo && oa_lo < ai_lo)) { mx_lo = om_lo; ai_lo = oa_lo; }
        if (om_hi > mx_hi || (om_hi == mx_hi && oa_hi < ai_hi)) { mx_hi = om_hi; ai_hi = oa_hi; }
    }
    if (tig == 0) {
        g_avg[mod][row0 + r_lo] = sum_lo * (1.0f / KC);
        g_assign[mod][row0 + r_lo] = ai_lo;
        g_avg[mod][row0 + r_hi] = sum_hi * (1.0f / KC);
        g_assign[mod][row0 + r_hi] = ai_hi;
    }
}

// ---------------- segment sums: SW-pipelined 8-row double buffer ----------
// One staging pass for all 112 rows, then loads for group g+1 issued BEFORE
// group g's exp+accumulate — DRAM latency hidden under the smem section.
__global__ __launch_bounds__(256, 4) void seg_kernel(const float* __restrict__ outp) {
    __shared__ float acc[NMOD * KC * 256];   // 46080 B
    __shared__ int   s_a0[SEG_ROWS], s_a1[SEG_ROWS], s_a2[SEG_ROWS];
    __shared__ float s_rm[SEG_ROWS], s_ri[SEG_ROWS];
    int tid = threadIdx.x;
    int c = blockIdx.x * 256 + tid;
    bool valid = c < C;
    for (int j = tid; j < NMOD * KC * 256; j += 256) acc[j] = 0.f;

    int r0 = blockIdx.y * SEG_ROWS;
    int rend = r0 + SEG_ROWS; if (rend > B) rend = B;
    int clen = rend - r0;                      // 112 or 32 or <=0 (mult of 8)

    if (clen > 0) {
        if (tid < clen) {
            s_a0[tid] = g_assign[0][r0 + tid] * 256;
            s_a1[tid] = (KC + g_assign[1][r0 + tid]) * 256;
            s_a2[tid] = (2 * KC + g_assign[2][r0 + tid]) * 256;
            s_rm[tid] = g_rmax[r0 + tid];
            s_ri[tid] = g_rinv[r0 + tid];
        }
        __syncthreads();
        if (valid) {
            const float* op = outp + (size_t)r0 * C + c;
            float p[8];
#pragma unroll
            for (int j = 0; j < 8; j++) p[j] = op[(size_t)j * C];
            for (int rr = 0; rr < clen; rr += 8) {
                float q[8];
                if (rr + 8 < clen) {
#pragma unroll
                    for (int j = 0; j < 8; j++)
                        q[j] = op[(size_t)(rr + 8 + j) * C];   // next group in flight
                }
#pragma unroll
                for (int j = 0; j < 8; j++)
                    p[j] = __expf(p[j] - s_rm[rr + j]) * s_ri[rr + j];
#pragma unroll
                for (int j = 0; j < 8; j++) {
                    acc[s_a0[rr + j] + tid] += p[j];
                    acc[s_a1[rr + j] + tid] += p[j];
                    acc[s_a2[rr + j] + tid] += p[j];
                }
#pragma unroll
                for (int j = 0; j < 8; j++) p[j] = q[j];
            }
        }
    }
    __syncthreads();
    if (valid && clen > 0) {
#pragma unroll
        for (int j = 0; j < NMOD * KC; j++)
            atomicAdd(&g_segsum[j][c], acc[j * 256 + tid]);
    }
}

// ---------------- radix select + attractive (smem-resident, s2) -----------
__global__ __launch_bounds__(1024) void select_attr_kernel(int rank0) {
    extern __shared__ unsigned int skeys[];       // 16384 u32 = 64 KB
    __shared__ unsigned int hist[256];
    __shared__ unsigned int sc[256];
    __shared__ unsigned int s_prefix;
    __shared__ int s_rank;
    __shared__ float s_thr;
    __shared__ float sred[32];

    int mod = blockIdx.x;
    const float* avg = g_avg[mod];
    int tid = threadIdx.x;
    int lane = tid & 31, warp = tid >> 5;

#pragma unroll
    for (int i = tid; i < B; i += 1024) {
        unsigned int u = __float_as_uint(avg[i]);
        skeys[i] = (u & 0x80000000u) ? ~u : (u | 0x80000000u);
    }
    if (tid == 0) { s_prefix = 0u; s_rank = rank0; }
    __syncthreads();

    for (int p = 3; p >= 0; p--) {
        if (tid < 256) hist[tid] = 0u;
        __syncthreads();
        unsigned int mask = (p == 3) ? 0u : (0xFFFFFFFFu << ((p + 1) * 8));
        unsigned int pref = s_prefix;
        int r = s_rank;
#pragma unroll
        for (int i = tid; i < B; i += 1024) {
            unsigned int u = skeys[i];
            if ((u & mask) == (pref & mask))
                atomicAdd(&hist[(u >> (p * 8)) & 255u], 1u);
        }
        __syncthreads();
        if (tid < 256) sc[tid] = hist[tid];
        __syncthreads();
#pragma unroll
        for (int off = 1; off < 256; off <<= 1) {
            unsigned int add = 0u;
            if (tid < 256 && tid >= off) add = sc[tid - off];
            __syncthreads();
            if (tid < 256) sc[tid] += add;
            __syncthreads();
        }
        if (tid < 256) {
            unsigned int inc = sc[tid], exc = inc - hist[tid];
            if ((unsigned int)r >= exc && (unsigned int)r < inc) {
                s_prefix = pref | ((unsigned int)tid << (p * 8));
                s_rank = r - (int)exc;
            }
        }
        __syncthreads();
    }
    if (tid == 0) {
        unsigned int u = s_prefix;
        unsigned int bits = (u & 0x80000000u) ? (u ^ 0x80000000u) : ~u;
        s_thr = __uint_as_float(bits);
    }
    __syncthreads();

    float thr = s_thr;
    float s = 0.f;
#pragma unroll
    for (int i = tid; i < B; i += 1024) {
        unsigned int u = skeys[i];
        unsigned int bits = (u & 0x80000000u) ? (u ^ 0x80000000u) : ~u;
        float a = __uint_as_float(bits);
        float w = 1.f / (1.f + expf(-5.0f * (a - thr)));   // ALPHA = 5
        s += w * (1.f - a);
    }
#pragma unroll
    for (int o = 16; o > 0; o >>= 1) s += __shfl_xor_sync(0xffffffffu, s, o);
    if (lane == 0) sred[warp] = s;
    __syncthreads();
    if (tid < 32) {
        float t = sred[tid];
#pragma unroll
        for (int o = 16; o > 0; o >>= 1) t += __shfl_xor_sync(0xffffffffu, t, o);
        if (tid == 0) g_attrpart[mod] = t;
    }
}

// ---------------- pure copy out -> d_out (s1, overlaps sim) ---------------
__global__ __launch_bounds__(256) void copy_kernel(const float* __restrict__ src,
                                                   float* __restrict__ dst) {
    size_t i = (size_t)blockIdx.x * 256 + threadIdx.x;
    size_t n4 = (size_t)B * C / 4;
    const float4* s4 = (const float4*)src;
    float4* d4 = (float4*)dst;
    for (; i < n4; i += (size_t)gridDim.x * 256) d4[i] = s4[i];
}

// ---------------- entropy + counts + finalize (ticket, main) --------------
__global__ void entropy_final_kernel(float* dout_last) {
    int bk = blockIdx.x;  // 0..44
    int mod = bk / KC, k = bk % KC;
    int tid = threadIdx.x;

    int cnt = 0;
    const int* as = g_assign[mod];
    for (int i = tid; i < B; i += 256) cnt += (as[i] == k);
    __shared__ int ci[256];
    ci[tid] = cnt; __syncthreads();
    for (int o = 128; o > 0; o >>= 1) {
        if (tid < o) ci[tid] += ci[tid + o];
        __syncthreads();
    }
    float fcnt = (float)ci[0];
    float inv = 1.f / fmaxf(fcnt, 1.f);

    float s = 0.f;
    for (int i = tid; i < C; i += 256) {
        float mp = g_segsum[bk][i] * inv;
        s += mp * __logf(mp + 1e-8f);
    }
    __shared__ float sm[256];
    sm[tid] = s; __syncthreads();
    for (int o = 128; o > 0; o >>= 1) {
        if (tid < o) sm[tid] += sm[tid + o];
        __syncthreads();
    }
    if (tid == 0) {
        g_entpart[bk] = (fcnt >= 3.0f) ? sm[0] : 0.f;
        __threadfence();
        int t = atomicAdd(&g_ticket, 1);
        if (t == NMOD * KC - 1) {
            __threadfence();
            float div = 0.f;
#pragma unroll
            for (int j = 0; j < NMOD * KC; j++) div += g_entpart[j];
            float attr = g_attrpart[0] + g_attrpart[1] + g_attrpart[2];
            // LAM_CLUSTER = 6.0, LAM_DIV = 0.1
            *dout_last = 6.0f * (attr / (float)B) + 0.1f * div;
        }
    }
}

// ---------------- launch: R11 graph exactly; seg in profile slot #4 -------
extern "C" void kernel_launch(void* const* d_in, const int* in_sizes, int n_in,
                              void* d_out, int out_size) {
    const float* f0 = (const float*)d_in[0];
    const float* f1 = (const float*)d_in[1];
    const float* f2 = (const float*)d_in[2];
    const float* c0 = (const float*)d_in[3];
    const float* c1 = (const float*)d_in[4];
    const float* c2 = (const float*)d_in[5];
    const float* outp = (const float*)d_in[6];
    float* dout = (float*)d_out;
    (void)n_in; (void)in_sizes;

    static cudaStream_t s1 = 0, s2 = 0;
    static cudaEvent_t ev_root = 0, ev_stats = 0, ev_copy = 0, ev_sim = 0, ev_sel = 0;
    if (s1 == 0) {
        cudaStreamCreateWithFlags(&s1, cudaStreamNonBlocking);
        cudaStreamCreateWithFlags(&s2, cudaStreamNonBlocking);
        cudaEventCreateWithFlags(&ev_root, cudaEventDisableTiming);
        cudaEventCreateWithFlags(&ev_stats, cudaEventDisableTiming);
        cudaEventCreateWithFlags(&ev_copy, cudaEventDisableTiming);
        cudaEventCreateWithFlags(&ev_sim, cudaEventDisableTiming);
        cudaEventCreateWithFlags(&ev_sel, cudaEventDisableTiming);
        cudaFuncSetAttribute(select_attr_kernel,
                             cudaFuncAttributeMaxDynamicSharedMemorySize, B * 4);
    }

    // fork to s1: init + stats (graph: concurrent with sim, like R11)
    cudaEventRecord(ev_root, 0);
    cudaStreamWaitEvent(s1, ev_root, 0);
    init_kernel<<<(NMOD * KC * C + 255) / 256, 256, 0, s1>>>();             // #1
    stats_kernel<<<B / 8, 256, 0, s1>>>(outp);                              // #2
    cudaEventRecord(ev_stats, s1);

    // main: sim
    sim_kernel<<<dim3(B / 128, NMOD), 256>>>(f0, f1, f2, c0, c1, c2);       // #3
    cudaEventRecord(ev_sim, 0);

    // main: seg (profile slot #4) — graph deps: stats + sim(same stream)
    cudaStreamWaitEvent(0, ev_stats, 0);
    seg_kernel<<<dim3(4, 148), 256>>>(outp);                                // #4

    // s1: copy — stream-ordered after stats => concurrent with sim (R11 graph)
    copy_kernel<<<2048, 256, 0, s1>>>(outp, dout);                          // #5
    cudaEventRecord(ev_copy, s1);

    // s2: select — depends only on sim
    cudaStreamWaitEvent(s2, ev_sim, 0);
    int rank0 = B - (int)((double)B * 0.6);   // = 6554
    select_attr_kernel<<<NMOD, 1024, B * 4, s2>>>(rank0);                   // #6
    cudaEventRecord(ev_sel, s2);

    // join select + copy, then entropy+finalize
    cudaStreamWaitEvent(0, ev_sel, 0);
    cudaStreamWaitEvent(0, ev_copy, 0);
    entropy_final_kernel<<<NMOD * KC, 256>>>(dout + (size_t)out_size - 1);  // #7
}